// round 2
// baseline (speedup 1.0000x reference)
#include <cuda_runtime.h>
#include <cstddef>

// Problem constants
#define A_ 4
#define B_ 8
#define S_ 2048
#define D_ 256
#define N_ 32      // A_*B_
#define H_ 256
#define G_ 1024    // 4*H_
#define P_ 64      // scan CTAs per direction
#define JH 4       // hidden units per scan CTA (H_/P_)
#define WPAD 20    // padded 16-float rows in smem

// -------- scratch (device globals; allocation-free per harness rules) --------
__device__ float g_f[(size_t)N_ * S_ * D_];
__device__ float g_xw0[(size_t)N_ * S_ * G_];
__device__ float g_xw1[(size_t)N_ * S_ * G_];
__device__ float g_hseq0[(size_t)N_ * S_ * H_];
__device__ float g_hseq1[(size_t)N_ * S_ * H_];
__device__ float g_hbuf[(size_t)N_ * S_ * D_];
__device__ float g_hstate[2][2][H_ * N_];   // [dir][buf][k*32 + n]
__device__ float g_zp[B_ * D_];
__device__ unsigned g_bar[4];               // [iter*2 + dir]

__device__ __forceinline__ float fsig(float x) { return 1.f / (1.f + __expf(-x)); }
__device__ __forceinline__ float ftanh(float x) {
    float t = __expf(-2.f * fabsf(x));
    float r = (1.f - t) / (1.f + t);
    return copysignf(r, x);
}

// ------------------------------- init ---------------------------------------
__global__ void k_init() {
    if (threadIdx.x < 4) g_bar[threadIdx.x] = 0u;
}

// ------------------------- z / zp (tiny matvec) ------------------------------
__global__ void k_zzp(const float* __restrict__ hin, const float* __restrict__ W4,
                      const float* __restrict__ b4) {
    __shared__ float zs[D_];
    int b = blockIdx.x;       // 0..7
    int e = threadIdx.x;      // 0..255
    float s = 0.f;
#pragma unroll
    for (int a = 0; a < A_; ++a)
        s += hin[(((size_t)(a * B_ + b)) * S_ + (S_ - 1)) * D_ + e];
    zs[e] = s * (1.f / 3.f);  // sum over agents / (A-1)
    __syncthreads();
    float acc = b4[e];
#pragma unroll 8
    for (int d = 0; d < D_; ++d) acc += zs[d] * W4[d * D_ + e];
    g_zp[b * D_ + e] = acc;
}

// ------------------------------ SGEMM ----------------------------------------
// C[M x NDIM] = op(A)[M x KDIM] @ Bw[KDIM x NDIM] + bias (+ optional zp + tanh)
// AMODE 0: A0[m][k]
// AMODE 1: A0[(n, S-1-s)][k]                (time-reversed rows; m = n*S+s)
// AMODE 2: k<256 -> A0[(n,s)][k] ; k>=256 -> A1[(n,S-1-s)][k-256]  (concat)
// EPI 0: +bias   EPI 1: tanh(v + bias + g_zp[b])
template <int AMODE, int EPI, int KDIM, int NDIM>
__global__ void __launch_bounds__(256, 2)
k_gemm(const float* __restrict__ A0, const float* __restrict__ A1,
       const float* __restrict__ Bw, const float* __restrict__ bias,
       float* __restrict__ C) {
    __shared__ float As[8][128];
    __shared__ float Bs[8][128];
    const int tid = threadIdx.x;
    const int m0 = blockIdx.y * 128;
    const int n0 = blockIdx.x * 128;
    const int aRow = tid >> 1;
    const int aCol = (tid & 1) * 4;
    const int bRow = tid >> 5;
    const int bCol = (tid & 31) * 4;
    const int tr = (tid >> 4) * 8;
    const int tc = (tid & 15) * 8;

    const int m = m0 + aRow;
    const float* aP0;
    const float* aP1 = nullptr;
    if (AMODE == 0) {
        aP0 = A0 + (size_t)m * KDIM;
    } else if (AMODE == 1) {
        int n = m >> 11, s = m & 2047;
        aP0 = A0 + ((size_t)(n << 11) + (2047 - s)) * KDIM;
    } else {
        int n = m >> 11, s = m & 2047;
        aP0 = A0 + (size_t)m * 256;
        aP1 = A1 + ((size_t)(n << 11) + (2047 - s)) * 256;
    }
    const float* bP = Bw + (size_t)bRow * NDIM + n0 + bCol;

    float acc[8][8];
#pragma unroll
    for (int i = 0; i < 8; ++i)
#pragma unroll
        for (int j = 0; j < 8; ++j) acc[i][j] = 0.f;

    for (int k0 = 0; k0 < KDIM; k0 += 8) {
        float4 av;
        if (AMODE < 2) {
            av = *(const float4*)(aP0 + k0 + aCol);
        } else {
            int kk = k0 + aCol;
            av = (kk < 256) ? *(const float4*)(aP0 + kk)
                            : *(const float4*)(aP1 + (kk - 256));
        }
        float4 bv = *(const float4*)(bP + (size_t)k0 * NDIM);
        As[aCol + 0][aRow] = av.x;
        As[aCol + 1][aRow] = av.y;
        As[aCol + 2][aRow] = av.z;
        As[aCol + 3][aRow] = av.w;
        *(float4*)&Bs[bRow][bCol] = bv;
        __syncthreads();
#pragma unroll
        for (int kk = 0; kk < 8; ++kk) {
            float ra[8], rb[8];
            *(float4*)(ra)     = *(const float4*)&As[kk][tr];
            *(float4*)(ra + 4) = *(const float4*)&As[kk][tr + 4];
            *(float4*)(rb)     = *(const float4*)&Bs[kk][tc];
            *(float4*)(rb + 4) = *(const float4*)&Bs[kk][tc + 4];
#pragma unroll
            for (int i = 0; i < 8; ++i)
#pragma unroll
                for (int j = 0; j < 8; ++j) acc[i][j] += ra[i] * rb[j];
        }
        __syncthreads();
    }

#pragma unroll
    for (int i = 0; i < 8; ++i) {
        int mm = m0 + tr + i;
        float* crow = C + (size_t)mm * NDIM + n0 + tc;
        int bi = 0;
        if (EPI == 1) bi = (mm >> 11) & 7;   // n = m>>11 ; b = n & 7
#pragma unroll
        for (int j4 = 0; j4 < 8; j4 += 4) {
            int col = n0 + tc + j4;
            float4 v = make_float4(acc[i][j4], acc[i][j4 + 1], acc[i][j4 + 2], acc[i][j4 + 3]);
            v.x += bias[col]; v.y += bias[col + 1]; v.z += bias[col + 2]; v.w += bias[col + 3];
            if (EPI == 1) {
                const float* zr = &g_zp[bi * D_];
                v.x = ftanh(v.x + zr[col]);     v.y = ftanh(v.y + zr[col + 1]);
                v.z = ftanh(v.z + zr[col + 2]); v.w = ftanh(v.w + zr[col + 3]);
            }
            *(float4*)(crow + j4) = v;
        }
    }
}

// --------------------------- persistent LSTM scan ----------------------------
// Grid: 128 CTAs. dir = blockIdx>>6 (0=fwd,1=bwd). Each CTA owns JH=4 hidden
// units -> 16 gate columns (c = jj*4 + {i,f,g,o}). Wh slice cached in smem.
// K=256 split across 8 warps; partials reduced through smem. c-state in regs.
// h state double-buffered in gmem (L2) with a per-step monotonic spin barrier.
__global__ void __launch_bounds__(256, 1)
k_scan(const float* __restrict__ Whf, const float* __restrict__ Whb, int barBase) {
    __shared__ float Wsl[256 * WPAD];
    __shared__ float red[256 * WPAD];
    const int tid = threadIdx.x;
    const int lane = tid & 31;
    const int w = tid >> 5;
    const int dir = blockIdx.x >> 6;
    const int blk = blockIdx.x & 63;
    const int j0 = blk * JH;
    const float* Wh = dir ? Whb : Whf;
    const float* xw = dir ? g_xw1 : g_xw0;
    float* hseq = dir ? g_hseq1 : g_hseq0;
    unsigned* bar = &g_bar[barBase + dir];

    // Load Wh slice: Wsl[k][jj*4+gt] = Wh[k][gt*256 + j0 + jj]
    {
        const float* wr = Wh + (size_t)tid * G_ + j0;
        float4 q0 = *(const float4*)(wr);
        float4 q1 = *(const float4*)(wr + 256);
        float4 q2 = *(const float4*)(wr + 512);
        float4 q3 = *(const float4*)(wr + 768);
        float* ws = &Wsl[tid * WPAD];
        ws[0]  = q0.x; ws[1]  = q1.x; ws[2]  = q2.x; ws[3]  = q3.x;
        ws[4]  = q0.y; ws[5]  = q1.y; ws[6]  = q2.y; ws[7]  = q3.y;
        ws[8]  = q0.z; ws[9]  = q1.z; ws[10] = q2.z; ws[11] = q3.z;
        ws[12] = q0.w; ws[13] = q1.w; ws[14] = q2.w; ws[15] = q3.w;
    }
    __syncthreads();

    const int wk0 = w * 32;
    float creg = 0.f;        // cell state (valid for tid<128)
    const int un = lane;     // batch index
    const int ujj = w;       // hidden sub-index (valid when w<4)

    for (int t = 0; t < S_; ++t) {
        // prefetch this step's input projection (overlaps with GEMM below)
        float xi = 0.f, xf = 0.f, xg = 0.f, xo = 0.f;
        if (tid < 128) {
            const float* xp = xw + ((size_t)un * S_ + t) * G_ + j0 + ujj;
            xi = __ldcg(xp);
            xf = __ldcg(xp + 256);
            xg = __ldcg(xp + 512);
            xo = __ldcg(xp + 768);
        }

        float acc[16];
#pragma unroll
        for (int c = 0; c < 16; ++c) acc[c] = 0.f;

        if (t > 0) {
            const float* hb = &g_hstate[dir][(t + 1) & 1][wk0 * N_ + lane];
            float hreg[32];
#pragma unroll
            for (int kk = 0; kk < 32; ++kk) hreg[kk] = __ldcg(hb + kk * N_);
#pragma unroll
            for (int kk = 0; kk < 32; ++kk) {
                const float4* wp = (const float4*)&Wsl[(wk0 + kk) * WPAD];
                float4 w0 = wp[0], w1 = wp[1], w2 = wp[2], w3 = wp[3];
                float hv = hreg[kk];
                acc[0]  += hv * w0.x; acc[1]  += hv * w0.y; acc[2]  += hv * w0.z; acc[3]  += hv * w0.w;
                acc[4]  += hv * w1.x; acc[5]  += hv * w1.y; acc[6]  += hv * w1.z; acc[7]  += hv * w1.w;
                acc[8]  += hv * w2.x; acc[9]  += hv * w2.y; acc[10] += hv * w2.z; acc[11] += hv * w2.w;
                acc[12] += hv * w3.x; acc[13] += hv * w3.y; acc[14] += hv * w3.z; acc[15] += hv * w3.w;
            }
        }

        {   // store K-partials
            float* rr = &red[tid * WPAD];
            ((float4*)rr)[0] = make_float4(acc[0], acc[1], acc[2], acc[3]);
            ((float4*)rr)[1] = make_float4(acc[4], acc[5], acc[6], acc[7]);
            ((float4*)rr)[2] = make_float4(acc[8], acc[9], acc[10], acc[11]);
            ((float4*)rr)[3] = make_float4(acc[12], acc[13], acc[14], acc[15]);
        }
        __syncthreads();

        if (tid < 128) {
            float4 s = make_float4(0.f, 0.f, 0.f, 0.f);
#pragma unroll
            for (int ww = 0; ww < 8; ++ww) {
                float4 v = *(const float4*)&red[(ww * 32 + un) * WPAD + ujj * 4];
                s.x += v.x; s.y += v.y; s.z += v.z; s.w += v.w;
            }
            float gi = s.x + xi, gf = s.y + xf, gg = s.z + xg, go = s.w + xo;
            float ii = fsig(gi), ff = fsig(gf);
            float g2 = ftanh(gg), oo = fsig(go);
            creg = ff * creg + ii * g2;
            float hv = oo * ftanh(creg);
            __stcg(&g_hstate[dir][t & 1][(j0 + ujj) * N_ + un], hv);
            hseq[((size_t)un * S_ + t) * H_ + j0 + ujj] = hv;
        }
        __threadfence();
        __syncthreads();

        if (t < S_ - 1) {
            if (tid == 0) {
                atomicAdd(bar, 1u);
                const unsigned target = (unsigned)(P_ * (t + 1));
                while (*((volatile unsigned*)bar) < target) { }
                __threadfence();
            }
            __syncthreads();
        }
    }
}

// ------------------------------ launcher -------------------------------------
extern "C" void kernel_launch(void* const* d_in, const int* in_sizes, int n_in,
                              void* d_out, int out_size) {
    const float* x   = (const float*)d_in[0];
    const float* W3  = (const float*)d_in[1];
    const float* b3  = (const float*)d_in[2];
    const float* W4  = (const float*)d_in[3];
    const float* b4  = (const float*)d_in[4];
    const float* Wxf = (const float*)d_in[5];
    const float* Whf = (const float*)d_in[6];
    const float* bf  = (const float*)d_in[7];
    const float* Wxb = (const float*)d_in[8];
    const float* Whb = (const float*)d_in[9];
    const float* bb  = (const float*)d_in[10];
    const float* Wd  = (const float*)d_in[11];
    const float* bd  = (const float*)d_in[12];
    float* out = (float*)d_out;

    float *pf, *pxw0, *pxw1, *ph0, *ph1, *phbuf;
    cudaGetSymbolAddress((void**)&pf,    g_f);
    cudaGetSymbolAddress((void**)&pxw0,  g_xw0);
    cudaGetSymbolAddress((void**)&pxw1,  g_xw1);
    cudaGetSymbolAddress((void**)&ph0,   g_hseq0);
    cudaGetSymbolAddress((void**)&ph1,   g_hseq1);
    cudaGetSymbolAddress((void**)&phbuf, g_hbuf);

    k_init<<<1, 32>>>();

    for (int it = 0; it < 2; ++it) {
        const float* hin = (it == 0) ? x : phbuf;
        float* hout = (it == 1) ? out : phbuf;

        // zp = (sum_a h[:, :, -1, :]/3) @ W4 + b4
        k_zzp<<<B_, D_>>>(hin, W4, b4);
        // f = tanh(h @ W3 + b3 + zp[b])
        k_gemm<0, 1, 256, 256><<<dim3(2, 512), 256>>>(hin, nullptr, W3, b3, pf);
        // gate input projections (fwd + time-reversed bwd)
        k_gemm<0, 0, 256, 1024><<<dim3(8, 512), 256>>>(pf, nullptr, Wxf, bf, pxw0);
        k_gemm<1, 0, 256, 1024><<<dim3(8, 512), 256>>>(pf, nullptr, Wxb, bb, pxw1);
        // persistent bidirectional LSTM scan
        k_scan<<<128, 256>>>(Whf, Whb, it * 2);
        // h = concat(hf, hb_rev) @ Wd + bd
        k_gemm<2, 0, 512, 256><<<dim3(2, 512), 256>>>(ph0, ph1, Wd, bd, hout);
    }
}